// round 14
// baseline (speedup 1.0000x reference)
#include <cuda_runtime.h>
#include <math.h>

#define BGR 32768
#define NPG 54
#define EPG 144
#define GLOB 10
#define F0 8
#define F1 16
#define F2 4
#define CAT 226   /* 54*4 + 10 */
#define H1 128
#define BM 64
#define WPG 4       /* graphs (warps) per gconv CTA */
#define NCHUNK 4
#define CHUNK (BGR / NCHUNK)   /* 8192 graphs per pipeline chunk */

// Scratch: concat([embeds, g]) per graph, [B, 226]
__device__ float g_emb[BGR * CAT];

// ---------------------------------------------------------------------------
// Kernel 1: warp-per-graph GraphConv x2 (+ ReLU) + global MLP.
// One WARP owns one graph (all phases warp-synchronous). conv1: aggregate
// (8-dim) -> linear. conv2: transform-first -> aggregate 4-dim messages.
// `gb` = first graph of this chunk.
// ---------------------------------------------------------------------------
__global__ void __launch_bounds__(128) gconv_kernel(
    int gb,
    const float* __restrict__ x,
    const int*   __restrict__ eidx,    // [2, E]
    const float* __restrict__ eattr,
    const float* __restrict__ gfeat,
    const float* __restrict__ W_rel1, const float* __restrict__ b1,
    const float* __restrict__ W_root1,
    const float* __restrict__ W_rel2, const float* __restrict__ b2,
    const float* __restrict__ W_root2,
    const float* __restrict__ Wg1, const float* __restrict__ bg1,
    const float* __restrict__ Wg2, const float* __restrict__ bg2,
    const float* __restrict__ Wg3, const float* __restrict__ bg3)
{
    const int tid  = threadIdx.x;
    const int w    = tid >> 5;         // warp slot = graph slot in CTA
    const int lane = tid & 31;
    const int b    = gb + blockIdx.x * WPG + w;

    __shared__ float4 sx4[WPG][NPG * 2];     // x        [54][8]  as float4
    __shared__ float4 sh4[WPG][NPG * 4];     // conv1 out [54][16]
    __shared__ float4 sagg4[WPG][NPG * 2];   // conv1 agg / conv2 {t, r}
    __shared__ float2 sedge[WPG][EPG];       // dst-sorted {attr, src}
    __shared__ int    soff[WPG][NPG + 2];
    __shared__ int    scur[WPG][NPG];
    __shared__ float  wr1[F0 * F1], wrt1[F0 * F1], sb1[F1];
    __shared__ float  wr2[F1 * F2], wrt2[F1 * F2], sb2[F2];
    __shared__ float  wg1[GLOB * 8], wg2[64], wg3[80];
    __shared__ float  sbg1[8], sbg2[8], sbg3[GLOB];

    // unsorted edge staging aliases this graph's sagg4 (dead after scatter)
    float* sattr_u = (float*)sagg4[w];         // [144]
    short* ssrc_u  = (short*)(sattr_u + EPG);  // [144]
    short* sdst_u  = ssrc_u + EPG;             // [144]
    float* shfp    = (float*)sh4[w];

    // ---- CTA-cooperative weight load (one bar.sync total) ----
    if (tid < F0 * F1) { wr1[tid] = W_rel1[tid]; wrt1[tid] = W_root1[tid]; }
    if (tid < F1 * F2) { wr2[tid] = W_rel2[tid]; wrt2[tid] = W_root2[tid]; }
    if (tid < F1) sb1[tid] = b1[tid];
    if (tid < F2) sb2[tid] = b2[tid];
    if (tid < GLOB * 8) wg1[tid] = Wg1[tid];
    if (tid < 64) wg2[tid] = Wg2[tid];
    if (tid < 80) wg3[tid] = Wg3[tid];
    if (tid < 8)  { sbg1[tid] = bg1[tid]; sbg2[tid] = bg2[tid]; }
    if (tid < GLOB) sbg3[tid] = bg3[tid];

    // ---- per-warp graph loads ----
    {
        const float4* xg = (const float4*)(x + (size_t)b * (NPG * F0));
        #pragma unroll
        for (int i = lane; i < NPG * 2; i += 32) sx4[w][i] = xg[i];
    }
    {
        const int*   srcg = eidx + (size_t)b * EPG;
        const int*   dstg = eidx + (size_t)BGR * EPG + (size_t)b * EPG;
        const float* ag   = eattr + (size_t)b * EPG;
        const int base = b * NPG;
        #pragma unroll
        for (int e = lane; e < EPG; e += 32) {
            sattr_u[e] = ag[e];
            ssrc_u[e]  = (short)(srcg[e] - base);
            sdst_u[e]  = (short)(dstg[e] - base);
        }
    }
    for (int i = lane; i < NPG; i += 32) scur[w][i] = 0;
    __syncthreads();                       // weights + own-graph staging ready

    // ---- degree counts (warp-local smem atomics) ----
    #pragma unroll
    for (int e = lane; e < EPG; e += 32) atomicAdd(&scur[w][sdst_u[e]], 1);
    __syncwarp();

    // ---- pair-wise shfl prefix scan over 54 counts ----
    {
        int c0 = 0, c1 = 0;
        if (lane < 27) { c0 = scur[w][2 * lane]; c1 = scur[w][2 * lane + 1]; }
        int s = c0 + c1, incl = s;
        #pragma unroll
        for (int o = 1; o < 32; o <<= 1) {
            int u = __shfl_up_sync(0xffffffffu, incl, o);
            if (lane >= o) incl += u;
        }
        int excl = incl - s;
        if (lane < 27) { soff[w][2 * lane] = excl; soff[w][2 * lane + 1] = excl + c0; }
        if (lane == 26) soff[w][NPG] = incl;       // = EPG
    }
    __syncwarp();
    for (int i = lane; i < NPG; i += 32) scur[w][i] = soff[w][i];
    __syncwarp();

    // ---- scatter edges into CSR slots ----
    #pragma unroll
    for (int e = lane; e < EPG; e += 32) {
        int slot = atomicAdd(&scur[w][sdst_u[e]], 1);
        float2 pe; pe.x = sattr_u[e]; pe.y = __int_as_float((int)ssrc_u[e]);
        sedge[w][slot] = pe;
    }

    // ---- global MLP, pure shuffles (runs while scatter drains) ----
    {
        float gv = (lane < GLOB) ? gfeat[(size_t)b * GLOB + lane] : 0.f;
        float v1 = (lane < 8) ? sbg1[lane] : 0.f;
        #pragma unroll
        for (int i = 0; i < GLOB; i++) {
            float gi = __shfl_sync(0xffffffffu, gv, i);
            if (lane < 8) v1 += gi * wg1[i * 8 + lane];
        }
        v1 = fmaxf(v1, 0.f);
        float v2 = (lane < 8) ? sbg2[lane] : 0.f;
        #pragma unroll
        for (int i = 0; i < 8; i++) {
            float vi = __shfl_sync(0xffffffffu, v1, i);
            if (lane < 8) v2 += vi * wg2[i * 8 + lane];
        }
        v2 = fmaxf(v2, 0.f);
        float v3 = (lane < GLOB) ? sbg3[lane] : 0.f;
        #pragma unroll
        for (int i = 0; i < 8; i++) {
            float vi = __shfl_sync(0xffffffffu, v2, i);
            if (lane < GLOB) v3 += vi * wg3[i * GLOB + lane];
        }
        if (lane < GLOB)
            g_emb[(size_t)b * CAT + NPG * F2 + lane] = fmaxf(v3, 0.f);
    }
    __syncwarp();     // sedge complete; staging (sagg4 alias) now dead

    // ---- conv1 aggregation: lane strides over (node, float4-half) ----
    #pragma unroll
    for (int it = lane; it < NPG * 2; it += 32) {
        int n = it >> 1, h = it & 1;
        float4 a = make_float4(0.f, 0.f, 0.f, 0.f);
        int k1 = soff[w][n + 1];
        for (int k = soff[w][n]; k < k1; k++) {
            float2 e = sedge[w][k];
            float4 xv = sx4[w][__float_as_int(e.y) * 2 + h];
            a.x += e.x * xv.x; a.y += e.x * xv.y;
            a.z += e.x * xv.z; a.w += e.x * xv.w;
        }
        sagg4[w][it] = a;          // layout [n][2]
    }
    __syncwarp();

    // ---- conv1 linear + ReLU: 16 cols x 2 n-groups, weights in regs ----
    {
        const int j = lane & 15, g2 = lane >> 4;    // g2 in 0..1
        float wc[16];
        const float bj = sb1[j];
        #pragma unroll
        for (int i = 0; i < F0; i++) { wc[i] = wr1[i * F1 + j]; wc[8 + i] = wrt1[i * F1 + j]; }
        for (int n = g2; n < NPG; n += 2) {
            float4 a0 = sagg4[w][n * 2], a1 = sagg4[w][n * 2 + 1];
            float4 x0 = sx4[w][n * 2],  x1 = sx4[w][n * 2 + 1];
            float v = bj;
            v += a0.x * wc[0] + a0.y * wc[1] + a0.z * wc[2] + a0.w * wc[3];
            v += a1.x * wc[4] + a1.y * wc[5] + a1.z * wc[6] + a1.w * wc[7];
            v += x0.x * wc[8] + x0.y * wc[9] + x0.z * wc[10] + x0.w * wc[11];
            v += x1.x * wc[12] + x1.y * wc[13] + x1.z * wc[14] + x1.w * wc[15];
            shfp[n * F1 + j] = fmaxf(v, 0.f);
        }
    }
    __syncwarp();

    // ---- conv2 TRANSFORM-FIRST: t[n][c] = h_n @ Wrel2, r[n][c] = b2 + h_n @ Wroot2
    {
        const int c = lane & 3, g2 = lane >> 2;     // g2 in 0..7
        float wa[16], wb[16];
        #pragma unroll
        for (int j = 0; j < F1; j++) { wa[j] = wr2[j * F2 + c]; wb[j] = wrt2[j * F2 + c]; }
        const float bc = sb2[c];
        for (int n = g2; n < NPG; n += 8) {
            float tr = 0.f, rr = bc;
            #pragma unroll
            for (int q = 0; q < 4; q++) {
                float4 h = sh4[w][n * 4 + q];
                tr += h.x * wa[q * 4 + 0] + h.y * wa[q * 4 + 1]
                    + h.z * wa[q * 4 + 2] + h.w * wa[q * 4 + 3];
                rr += h.x * wb[q * 4 + 0] + h.y * wb[q * 4 + 1]
                    + h.z * wb[q * 4 + 2] + h.w * wb[q * 4 + 3];
            }
            ((float*)&sagg4[w][n])[c]       = tr;
            ((float*)&sagg4[w][NPG + n])[c] = rr;
        }
    }
    __syncwarp();

    // ---- conv2 aggregate 4-dim messages + fused output store ----
    for (int n = lane; n < NPG; n += 32) {
        float4 a = make_float4(0.f, 0.f, 0.f, 0.f);
        int k1 = soff[w][n + 1];
        for (int k = soff[w][n]; k < k1; k++) {
            float2 e = sedge[w][k];
            float4 tv = sagg4[w][__float_as_int(e.y)];
            a.x += e.x * tv.x; a.y += e.x * tv.y;
            a.z += e.x * tv.z; a.w += e.x * tv.w;
        }
        float4 r = sagg4[w][NPG + n];
        float2 lo = make_float2(fmaxf(a.x + r.x, 0.f), fmaxf(a.y + r.y, 0.f));
        float2 hi = make_float2(fmaxf(a.z + r.z, 0.f), fmaxf(a.w + r.w, 0.f));
        float* dst = g_emb + (size_t)b * CAT + n * F2;
        *(float2*)dst       = lo;
        *(float2*)(dst + 2) = hi;
    }
}

// ---------------------------------------------------------------------------
// Kernel 2: head.  out = sigmoid( relu(concat @ Wo1 + bo1) @ Wo2 + bo2 )
// 64x128 tile, 128 threads, 8x8 microtile — ~91% of the scalar FFMA
// roofline. `rb` = first row (graph) of this chunk.
// ---------------------------------------------------------------------------
__global__ void __launch_bounds__(128) head_kernel(
    int rb,
    const float* __restrict__ Wo1, const float* __restrict__ bo1,
    const float* __restrict__ Wo2, const float* __restrict__ bo2,
    float* __restrict__ out)
{
    constexpr int BK = 16;
    __shared__ __align__(16) float  As[BK][BM + 4];   // padded, float4-readable
    __shared__ __align__(16) float4 Bs4[BK][32];      // [BK][128] floats
    __shared__ float  red[BM][17];

    const int rowBase = rb + blockIdx.x * BM;
    const int tid = threadIdx.x;
    const int tx = tid & 15, ty = tid >> 4;           // ty 0..7

    float acc[8][8];
    #pragma unroll
    for (int i = 0; i < 8; i++)
        #pragma unroll
        for (int j = 0; j < 8; j++) acc[i][j] = 0.f;

    const float* A = g_emb + (size_t)rowBase * CAT;

    for (int k0 = 0; k0 < CAT; k0 += BK) {
        #pragma unroll
        for (int l = 0; l < 8; l++) {                 // A: 64x16 scalars
            int idx = tid + l * 128;
            int row = idx >> 4, kk = idx & 15;
            int k = k0 + kk;
            As[kk][row] = (k < CAT) ? A[(size_t)row * CAT + k] : 0.f;
        }
        #pragma unroll
        for (int l = 0; l < 4; l++) {                 // B: 16x128 via float4
            int idx = tid + l * 128;
            int kk = idx >> 5, c4 = idx & 31;
            int k = k0 + kk;
            Bs4[kk][c4] = (k < CAT) ? *(const float4*)&Wo1[(size_t)k * H1 + c4 * 4]
                                    : make_float4(0.f, 0.f, 0.f, 0.f);
        }
        __syncthreads();
        #pragma unroll
        for (int kk = 0; kk < BK; kk++) {
            float4 a0 = *(const float4*)&As[kk][ty * 8];
            float4 a1 = *(const float4*)&As[kk][ty * 8 + 4];
            float4 b0 = Bs4[kk][tx * 2];
            float4 b1 = Bs4[kk][tx * 2 + 1];
            float av[8] = {a0.x, a0.y, a0.z, a0.w, a1.x, a1.y, a1.z, a1.w};
            float bv[8] = {b0.x, b0.y, b0.z, b0.w, b1.x, b1.y, b1.z, b1.w};
            #pragma unroll
            for (int i = 0; i < 8; i++)
                #pragma unroll
                for (int j = 0; j < 8; j++)
                    acc[i][j] += av[i] * bv[j];
        }
        __syncthreads();
    }

    // epilogue: bias + relu + dot(Wo2) partials, then cross-column reduce
    float bb[8], w2[8];
    #pragma unroll
    for (int j = 0; j < 8; j++) { bb[j] = bo1[tx * 8 + j]; w2[j] = Wo2[tx * 8 + j]; }
    #pragma unroll
    for (int i = 0; i < 8; i++) {
        float p = 0.f;
        #pragma unroll
        for (int j = 0; j < 8; j++) {
            float v = fmaxf(acc[i][j] + bb[j], 0.f);
            p += v * w2[j];
        }
        red[ty * 8 + i][tx] = p;
    }
    __syncthreads();
    if (tid < BM) {
        float s = bo2[0];
        #pragma unroll
        for (int t = 0; t < 16; t++) s += red[tid][t];
        out[rowBase + tid] = 1.f / (1.f + expf(-s));
    }
}

// ---------------------------------------------------------------------------
// Launch: 4-chunk software pipeline across two streams.
//   stream0: gconv(c0) gconv(c1) gconv(c2) gconv(c3)
//   s2:               head(c0)  head(c1)  head(c2)  head(c3)
// Events fork after each gconv chunk and join s2 back to stream0 at the end.
// Streams/events are created on the FIRST call (the uncaptured correctness
// run); during graph capture the record/wait pairs become graph edges
// (standard fork/join capture pattern). Events use DisableTiming, required
// for capture legality.
// ---------------------------------------------------------------------------
extern "C" void kernel_launch(void* const* d_in, const int* in_sizes, int n_in,
                              void* d_out, int out_size)
{
    const float* x       = (const float*)d_in[0];
    const int*   eidx    = (const int*)  d_in[1];
    const float* eattr   = (const float*)d_in[2];
    const float* gfeat   = (const float*)d_in[3];
    const float* W_rel1  = (const float*)d_in[4];
    const float* b1      = (const float*)d_in[5];
    const float* W_root1 = (const float*)d_in[6];
    const float* W_rel2  = (const float*)d_in[7];
    const float* b2      = (const float*)d_in[8];
    const float* W_root2 = (const float*)d_in[9];
    const float* Wg1     = (const float*)d_in[10];
    const float* bg1     = (const float*)d_in[11];
    const float* Wg2     = (const float*)d_in[12];
    const float* bg2     = (const float*)d_in[13];
    const float* Wg3     = (const float*)d_in[14];
    const float* bg3     = (const float*)d_in[15];
    const float* Wo1     = (const float*)d_in[16];
    const float* bo1     = (const float*)d_in[17];
    const float* Wo2     = (const float*)d_in[18];
    const float* bo2     = (const float*)d_in[19];
    float* out = (float*)d_out;

    static cudaStream_t s2 = nullptr;
    static cudaEvent_t  evg[NCHUNK];
    static cudaEvent_t  evjoin = nullptr;
    if (s2 == nullptr) {
        cudaStreamCreateWithFlags(&s2, cudaStreamNonBlocking);
        for (int c = 0; c < NCHUNK; c++)
            cudaEventCreateWithFlags(&evg[c], cudaEventDisableTiming);
        cudaEventCreateWithFlags(&evjoin, cudaEventDisableTiming);
    }

    for (int c = 0; c < NCHUNK; c++) {
        gconv_kernel<<<CHUNK / WPG, 128>>>(c * CHUNK,
                                           x, eidx, eattr, gfeat,
                                           W_rel1, b1, W_root1,
                                           W_rel2, b2, W_root2,
                                           Wg1, bg1, Wg2, bg2, Wg3, bg3);
        cudaEventRecord(evg[c], 0);
        cudaStreamWaitEvent(s2, evg[c], 0);
        head_kernel<<<CHUNK / BM, 128, 0, s2>>>(c * CHUNK,
                                                Wo1, bo1, Wo2, bo2, out);
    }
    cudaEventRecord(evjoin, s2);
    cudaStreamWaitEvent(0, evjoin, 0);
}